// round 17
// baseline (speedup 1.0000x reference)
#include <cuda_runtime.h>
#include <cuda_fp16.h>

typedef unsigned int u32;
typedef unsigned short u16;
typedef unsigned long long u64;

#define N_IMG 8
#define HH 128
#define WW 128
#define PLANE (N_IMG*HH*WW*64)
#define CHUNK_W (18*4096)          // fp16 elems per conv-chunk weight block (147456 B)
#define RING_SLOT 16896            // one row: 2 planes x 66 px x 128 B
#define DYN_SMEM (147456 + 4*RING_SLOT + 128)

// ---------------- scratch ----------------
__device__ __half g_Hh[PLANE], g_Hl[PLANE];
__device__ __half g_Ah[PLANE], g_Al[PLANE];
__device__ __half g_Bh[PLANE], g_Bl[PLANE];
__device__ float g_Hf[PLANE], g_Af[PLANE];
__device__ float g_S[N_IMG*100*256*256];
__device__ __half g_Wp[40*CHUNK_W];

// ---------------- helpers ----------------
__device__ __forceinline__ u32 smem_u32(const void* p){
    u32 a; asm("{ .reg .u64 t; cvta.to.shared.u64 t, %1; cvt.u32.u64 %0, t; }":"=r"(a):"l"(p)); return a;
}
__device__ __forceinline__ void ldsm4(u32* r, u32 addr){
    asm volatile("ldmatrix.sync.aligned.m8n8.x4.shared.b16 {%0,%1,%2,%3}, [%4];"
        : "=r"(r[0]),"=r"(r[1]),"=r"(r[2]),"=r"(r[3]) : "r"(addr));
}
__device__ __forceinline__ void ldsm4t(u32* r, u32 addr){
    asm volatile("ldmatrix.sync.aligned.m8n8.x4.trans.shared.b16 {%0,%1,%2,%3}, [%4];"
        : "=r"(r[0]),"=r"(r[1]),"=r"(r[2]),"=r"(r[3]) : "r"(addr));
}
// main term: fp16 inputs, fp32 accumulate (rt 8)
__device__ __forceinline__ void mma_f32(float* c, const u32* a, const u32* b){
    asm volatile("mma.sync.aligned.m16n8k16.row.col.f32.f16.f16.f32 "
        "{%0,%1,%2,%3}, {%4,%5,%6,%7}, {%8,%9}, {%0,%1,%2,%3};"
        : "+f"(c[0]),"+f"(c[1]),"+f"(c[2]),"+f"(c[3])
        : "r"(a[0]),"r"(a[1]),"r"(a[2]),"r"(a[3]), "r"(b[0]),"r"(b[1]));
}
// correction terms: fp16 inputs, fp16 accumulate (rt 4, double rate)
__device__ __forceinline__ void mma_f16(u32* c, const u32* a, const u32* b){
    asm volatile("mma.sync.aligned.m16n8k16.row.col.f16.f16.f16.f16 "
        "{%0,%1}, {%2,%3,%4,%5}, {%6,%7}, {%0,%1};"
        : "+r"(c[0]),"+r"(c[1])
        : "r"(a[0]),"r"(a[1]),"r"(a[2]),"r"(a[3]), "r"(b[0]),"r"(b[1]));
}
__device__ __forceinline__ void cp16(u32 dst, const void* src, bool ok){
    int sz = ok ? 16 : 0;
    asm volatile("cp.async.cg.shared.global [%0], [%1], 16, %2;"
        :: "r"(dst), "l"(src), "r"(sz));
}
#define CP_COMMIT() asm volatile("cp.async.commit_group;" ::: "memory")
#define CP_WAIT(n)  asm volatile("cp.async.wait_group %0;" :: "n"(n) : "memory")

// ---------------- weight prepack (fp16 hi/lo) ----------------
__global__ __launch_bounds__(256) void prepack_w(
    const float* __restrict__ src, __half* __restrict__ dst,
    int cout, int conv_stride, int nchunks)
{
    int conv = blockIdx.z, chunk = blockIdx.y;
    int idx = blockIdx.x*256 + threadIdx.x;
    if (idx >= CHUNK_W) return;
    int tile = idx >> 12, r = idx & 4095;
    int oc = r >> 6, ic = r & 63;
    int tap = tile >> 1, pl = tile & 1;
    int dy = tap/3, dx = tap%3;
    int ocg = chunk*64 + oc;
    float wv = (ocg < cout) ? src[(size_t)conv*conv_stride + ((size_t)ocg*64 + ic)*9 + dy*3 + dx] : 0.f;
    __half h = __float2half_rn(wv);
    __half v = pl ? __float2half_rn(wv - __half2float(h)) : h;
    int elem = tile*4096 + ic*64 + ((((oc>>3) ^ (ic&7)) << 3) | (oc & 7));
    dst[(size_t)(conv*nchunks + chunk)*CHUNK_W + elem] = v;
}

// ---------------- head: 3->64 fp32, out NHWC fp16 hi/lo + f32 ----------------
__global__ __launch_bounds__(256) void head_tc(
    const float* __restrict__ x, const float* __restrict__ w, const float* __restrict__ b,
    __half* __restrict__ oh, __half* __restrict__ ol, float* __restrict__ of)
{
    __shared__ float w_s[64*27];
    for (int i = threadIdx.x; i < 64*27; i += 256) w_s[i] = w[i];
    __syncthreads();
    int idx = blockIdx.x*256 + threadIdx.x;      // over 8*128*128
    int px = idx & 127, y = (idx >> 7) & 127, n = idx >> 14;
    const float mean[3] = {0.4488f*255.f, 0.4371f*255.f, 0.404f*255.f};
    float iv[27];
    #pragma unroll
    for (int ic = 0; ic < 3; ic++)
        #pragma unroll
        for (int dy = 0; dy < 3; dy++)
            #pragma unroll
            for (int dx = 0; dx < 3; dx++) {
                int gy = y + dy - 1, gx = px + dx - 1;
                float v = 0.f;
                if ((unsigned)gy < 128 && (unsigned)gx < 128)
                    v = x[((n*3 + ic)*128 + gy)*128 + gx] - mean[ic];
                iv[ic*9 + dy*3 + dx] = v;
            }
    size_t base = (size_t)idx * 64;
    for (int oc = 0; oc < 64; oc++) {
        float acc = b[oc];
        #pragma unroll
        for (int t = 0; t < 27; t++) acc += iv[t] * w_s[oc*27 + t];
        __half h = __float2half_rn(acc);
        oh[base + oc] = h;
        ol[base + oc] = __float2half_rn(acc - __half2float(h));
        of[base + oc] = acc;
    }
}

// ---------------- mma.sync conv v6 (fp16 split, dual-rate terms) ----------------
// Main Ah*Wh: f32-accum MMA (rt8). Corrections Al*Wh + Ah*Wl: shared f16-accum
// MMA (rt4). Per-np issue: 4*8 + 8*4 = 64cyc vs 96 for 3x bf16 -> ~1.5x conv.
template <bool RELU, bool RES, bool F32O, bool SHUF>
__global__ __launch_bounds__(128, 1) void conv_mma(
    const __half* __restrict__ in_h, const __half* __restrict__ in_l,
    const __half* __restrict__ wp, const float* __restrict__ bias,
    const float* __restrict__ resf,
    __half* __restrict__ out_h, __half* __restrict__ out_l,
    float* __restrict__ out_f, float* __restrict__ out_s)
{
    extern __shared__ char dyn[];
    __shared__ float bias_s[64];
    const int tid = threadIdx.x, w = tid >> 5, lane = tid & 31;
    const int y0 = blockIdx.x * 16;
    const int half_ = blockIdx.y >> 3, n = blockIdx.y & 7;
    const int chunk = blockIdx.z;
    const int px0 = half_ * 64;

    u32 sb = smem_u32(dyn);
    u32 W_sa = (sb + 127) & ~127u;
    u32 ring_sa = W_sa + 147456;

    // async weight load (147456 B)
    {
        const char* wsrc = (const char*)(wp + (size_t)chunk * CHUNK_W);
        #pragma unroll 8
        for (int i = tid; i < 9216; i += 128)
            cp16(W_sa + i*16, wsrc + (size_t)i*16, true);
        if (tid < 64) bias_s[tid] = bias[chunk*64 + tid];
    }

    auto load_row = [&](int rg){
        u32 dst0 = ring_sa + (u32)(rg & 3) * RING_SLOT;
        bool rok = ((unsigned)rg < 128u);
        #pragma unroll 2
        for (int i = tid; i < 528; i += 128) {
            int px = i >> 3, c = i & 7;
            int pg = px0 + px - 1;
            bool ok = rok && ((unsigned)pg < 128u);
            size_t off = ok ? (((size_t)((n*128 + rg)*128 + pg))*64 + c*8) : 0;
            u32 d = dst0 + px*128 + ((c ^ (px & 7)) << 4);
            cp16(d, in_h + off, ok);
            cp16(d + 8448, in_l + off, ok);
        }
    };

    load_row(y0 - 1); load_row(y0); load_row(y0 + 1);
    CP_COMMIT();
    CP_WAIT(0);
    __syncthreads();

    const int bk = lane & 15, bsw = bk & 7, bh2 = lane >> 4;

    for (int yb = y0; yb < y0 + 16; yb += 2) {
        load_row(yb + 2);          // group A
        CP_COMMIT();

        float accm[2][8][4];       // main term, fp32
        u32   accc[2][8][2];       // corrections, f16x2 packed (d0: rows r, d1: rows r+8)
        #pragma unroll
        for (int rr = 0; rr < 2; rr++)
            #pragma unroll
            for (int t = 0; t < 8; t++) {
                accm[rr][t][0]=accm[rr][t][1]=accm[rr][t][2]=accm[rr][t][3]=0.f;
                accc[rr][t][0]=accc[rr][t][1]=0u;
            }

        auto taps = [&](int dy, int s0, int s1){
            u32 sl0 = ring_sa + (u32)s0 * RING_SLOT;
            u32 sl1 = ring_sa + (u32)s1 * RING_SLOT;
            #pragma unroll 1
            for (int dx = 0; dx < 3; dx++) {
                int ar = w*16 + dx + bk;
                u32 arow0 = sl0 + ar*128, arow1 = sl1 + ar*128;
                u32 tapo = W_sa + (u32)((dy*3 + dx) * 2) * 8192u;
                #pragma unroll
                for (int kc = 0; kc < 4; kc++) {
                    u32 csel = (u32)((((kc << 1) | bh2) ^ (ar & 7)) << 4);
                    u32 a0h[4], a0l[4], a1h[4], a1l[4];
                    ldsm4(a0h, arow0 + csel);
                    ldsm4(a0l, arow0 + 8448 + csel);
                    ldsm4(a1h, arow1 + csel);
                    ldsm4(a1l, arow1 + 8448 + csel);
                    u32 brh = tapo + (u32)(kc*16 + bk) * 128u;
                    u32 bfh[2][4], bfl[2][4];
                    {
                        u32 co = (u32)((bh2 ^ bsw) << 4);
                        ldsm4t(bfh[0], brh + co);
                        ldsm4t(bfl[0], brh + 8192u + co);
                    }
                    #pragma unroll
                    for (int np = 0; np < 4; np++) {
                        const int cur = np & 1, nxt = cur ^ 1;
                        if (np < 3) {
                            u32 co = (u32)(((((np+1)*2) + bh2) ^ bsw) << 4);
                            ldsm4t(bfh[nxt], brh + co);
                            ldsm4t(bfl[nxt], brh + 8192u + co);
                        }
                        u32* bh_ = bfh[cur];
                        u32* bl_ = bfl[cur];
                        // main term: fp32 accumulate (rt8)
                        mma_f32(accm[0][np*2],   a0h, bh_);
                        mma_f32(accm[0][np*2+1], a0h, bh_+2);
                        mma_f32(accm[1][np*2],   a1h, bh_);
                        mma_f32(accm[1][np*2+1], a1h, bh_+2);
                        // corrections: f16 accumulate (rt4), shared accumulator
                        mma_f16(accc[0][np*2],   a0l, bh_);
                        mma_f16(accc[0][np*2+1], a0l, bh_+2);
                        mma_f16(accc[1][np*2],   a1l, bh_);
                        mma_f16(accc[1][np*2+1], a1l, bh_+2);
                        mma_f16(accc[0][np*2],   a0h, bl_);
                        mma_f16(accc[0][np*2+1], a0h, bl_+2);
                        mma_f16(accc[1][np*2],   a1h, bl_);
                        mma_f16(accc[1][np*2+1], a1h, bl_+2);
                    }
                }
            }
        };

        // dy=0: input rows yb-1, yb
        taps(0, (yb-1)&3, yb&3);
        __syncthreads();           // dy=0 readers done -> slot (yb+3)&3 free
        load_row(yb + 3);          // group B
        CP_COMMIT();
        CP_WAIT(2);                // row yb+1 (B of prev iter) complete
        __syncthreads();
        // dy=1: input rows yb, yb+1
        taps(1, yb&3, (yb+1)&3);
        CP_WAIT(1);                // row yb+2 (A) complete
        __syncthreads();           // also orders dy=1 readers vs next iter head cp.async
        // dy=2: input rows yb+1, yb+2
        taps(2, (yb+1)&3, (yb+2)&3);

        // direct register epilogue
        const int cb = (lane & 3) * 2;
        #pragma unroll
        for (int rr = 0; rr < 2; rr++) {
            int yy = yb + rr;
            #pragma unroll
            for (int h = 0; h < 2; h++) {
                int pg = px0 + w*16 + (lane >> 2) + h*8;
                size_t base = ((size_t)((n*128 + yy)*128 + pg))*64 + cb;
                if (SHUF) {
                    #pragma unroll
                    for (int nt = 0; nt < 8; nt++) {
                        __half2 cc = *(__half2*)&accc[rr][nt][h];
                        float v0 = accm[rr][nt][2*h]   + __half2float(__low2half(cc))  + bias_s[nt*8 + cb];
                        float v1 = accm[rr][nt][2*h+1] + __half2float(__high2half(cc)) + bias_s[nt*8 + cb + 1];
                        int oc0 = chunk*64 + nt*8 + cb;   // even; oc1 = oc0+1 shares (k,a)
                        if (oc0 < 400) {
                            int kk = oc0 >> 2, aa = (oc0 >> 1) & 1;
                            *(float2*)&out_s[((size_t)(n*100 + kk)*256 + (2*yy + aa))*256 + 2*pg] =
                                make_float2(v0, v1);
                        }
                    }
                } else {
                    #pragma unroll
                    for (int nt = 0; nt < 8; nt++) {
                        __half2 cc = *(__half2*)&accc[rr][nt][h];
                        float v0 = accm[rr][nt][2*h]   + __half2float(__low2half(cc))  + bias_s[nt*8 + cb];
                        float v1 = accm[rr][nt][2*h+1] + __half2float(__high2half(cc)) + bias_s[nt*8 + cb + 1];
                        if (RELU) { v0 = fmaxf(v0, 0.f); v1 = fmaxf(v1, 0.f); }
                        if (RES) {
                            float2 r2 = *(const float2*)(resf + base + nt*8);
                            v0 += r2.x; v1 += r2.y;
                        }
                        __half h0 = __float2half_rn(v0);
                        __half h1 = __float2half_rn(v1);
                        __half q0 = __float2half_rn(v0 - __half2float(h0));
                        __half q1 = __float2half_rn(v1 - __half2float(h1));
                        *(u32*)(out_h + base + nt*8) =
                            (u32)__half_as_ushort(h0) | ((u32)__half_as_ushort(h1) << 16);
                        *(u32*)(out_l + base + nt*8) =
                            (u32)__half_as_ushort(q0) | ((u32)__half_as_ushort(q1) << 16);
                        if (F32O)
                            *(float2*)(out_f + base + nt*8) = make_float2(v0, v1);
                    }
                }
            }
        }
        // no trailing barrier: pre-dy2 barrier provides the WAR edge for slot yb&3
    }
}

// ---------------- tail v2: 100 -> 3 on 256x256, smem-tiled ----------------
#define TIC 20
__global__ __launch_bounds__(256) void tail_kernel(
    const float* __restrict__ in, const float* __restrict__ w,
    const float* __restrict__ b, float* __restrict__ out)
{
    __shared__ float w_s[2700];
    __shared__ float t_s[TIC][18][18];
    const int tx = threadIdx.x & 15, ty = threadIdx.x >> 4;
    const int x0 = blockIdx.x * 16, y0 = blockIdx.y * 16, n = blockIdx.z;

    for (int i = threadIdx.x; i < 2700; i += 256) w_s[i] = w[i];

    float a0 = b[0], a1 = b[1], a2 = b[2];
    for (int c0 = 0; c0 < 100; c0 += TIC) {
        __syncthreads();
        for (int i = threadIdx.x; i < TIC*324; i += 256) {
            int ic = i / 324, rem = i - ic*324;
            int r = rem / 18, c = rem - r*18;
            int gy = y0 + r - 1, gx = x0 + c - 1;
            float v = 0.f;
            if ((unsigned)gy < 256 && (unsigned)gx < 256)
                v = in[((size_t)(n*100 + c0 + ic) * 256 + gy) * 256 + gx];
            t_s[ic][r][c] = v;
        }
        __syncthreads();
        #pragma unroll 4
        for (int ic = 0; ic < TIC; ic++) {
            int t = (c0 + ic) * 9;
            #pragma unroll
            for (int dy = 0; dy < 3; dy++) {
                #pragma unroll
                for (int dx = 0; dx < 3; dx++) {
                    float v = t_s[ic][ty + dy][tx + dx];
                    int k = t + dy*3 + dx;
                    a0 += v * w_s[k];
                    a1 += v * w_s[900 + k];
                    a2 += v * w_s[1800 + k];
                }
            }
        }
    }
    int X = x0 + tx, Y = y0 + ty;
    out[((size_t)(n*3 + 0)*256 + Y)*256 + X] = a0 + 0.4488f*255.f;
    out[((size_t)(n*3 + 1)*256 + Y)*256 + X] = a1 + 0.4371f*255.f;
    out[((size_t)(n*3 + 2)*256 + Y)*256 + X] = a2 + 0.404f*255.f;
}

// ---------------- launch ----------------
extern "C" void kernel_launch(void* const* d_in, const int* in_sizes, int n_in,
                              void* d_out, int out_size)
{
    const float* x       = (const float*)d_in[0];
    const float* head_w  = (const float*)d_in[1];
    const float* head_b  = (const float*)d_in[2];
    const float* rb_w1   = (const float*)d_in[3];
    const float* rb_b1   = (const float*)d_in[4];
    const float* rb_w2   = (const float*)d_in[5];
    const float* rb_b2   = (const float*)d_in[6];
    const float* body_w  = (const float*)d_in[7];
    const float* body_b  = (const float*)d_in[8];
    const float* super_w = (const float*)d_in[9];
    const float* super_b = (const float*)d_in[10];
    const float* out_w   = (const float*)d_in[11];
    const float* out_b   = (const float*)d_in[12];
    float* out = (float*)d_out;

    __half *pHh,*pHl,*pAh,*pAl,*pBh,*pBl,*pW;
    float *pHf,*pAf,*pS;
    cudaGetSymbolAddress((void**)&pHh, g_Hh); cudaGetSymbolAddress((void**)&pHl, g_Hl);
    cudaGetSymbolAddress((void**)&pAh, g_Ah); cudaGetSymbolAddress((void**)&pAl, g_Al);
    cudaGetSymbolAddress((void**)&pBh, g_Bh); cudaGetSymbolAddress((void**)&pBl, g_Bl);
    cudaGetSymbolAddress((void**)&pHf, g_Hf); cudaGetSymbolAddress((void**)&pAf, g_Af);
    cudaGetSymbolAddress((void**)&pS,  g_S);  cudaGetSymbolAddress((void**)&pW,  g_Wp);

    cudaFuncSetAttribute(conv_mma<true,false,false,false>, cudaFuncAttributeMaxDynamicSharedMemorySize, DYN_SMEM);
    cudaFuncSetAttribute(conv_mma<false,true,true,false>,  cudaFuncAttributeMaxDynamicSharedMemorySize, DYN_SMEM);
    cudaFuncSetAttribute(conv_mma<false,true,false,false>, cudaFuncAttributeMaxDynamicSharedMemorySize, DYN_SMEM);
    cudaFuncSetAttribute(conv_mma<false,false,false,true>, cudaFuncAttributeMaxDynamicSharedMemorySize, DYN_SMEM);

    // weight prepack
    prepack_w<<<dim3(288,1,16), 256>>>(rb_w1, pW,                64, 64*64*9, 1);
    prepack_w<<<dim3(288,1,16), 256>>>(rb_w2, pW + 16*CHUNK_W,   64, 64*64*9, 1);
    prepack_w<<<dim3(288,1,1),  256>>>(body_w, pW + (size_t)32*CHUNK_W, 64, 0, 1);
    prepack_w<<<dim3(288,7,1),  256>>>(super_w, pW + (size_t)33*CHUNK_W, 400, 0, 7);

    head_tc<<<(N_IMG*HH*WW)/256, 256>>>(x, head_w, head_b, pHh, pHl, pHf);

    dim3 grid(8, 16, 1);
    const __half *ch = pHh, *cl = pHl;
    const float* cf = pHf;
    for (int i = 0; i < 16; i++) {
        conv_mma<true,false,false,false><<<grid, 128, DYN_SMEM>>>(
            ch, cl, pW + (size_t)i*CHUNK_W, rb_b1 + i*64, nullptr,
            pBh, pBl, nullptr, nullptr);
        conv_mma<false,true,true,false><<<grid, 128, DYN_SMEM>>>(
            pBh, pBl, pW + (size_t)(16+i)*CHUNK_W, rb_b2 + i*64, cf,
            pAh, pAl, pAf, nullptr);
        ch = pAh; cl = pAl; cf = pAf;
    }
    // body: conv(A) + H -> B planes
    conv_mma<false,true,false,false><<<grid, 128, DYN_SMEM>>>(
        pAh, pAl, pW + (size_t)32*CHUNK_W, body_b, pHf,
        pBh, pBl, nullptr, nullptr);
    // super: 7 chunks, fused pixel-shuffle -> g_S
    conv_mma<false,false,false,true><<<dim3(8, 16, 7), 128, DYN_SMEM>>>(
        pBh, pBl, pW + (size_t)33*CHUNK_W, super_b, nullptr,
        nullptr, nullptr, nullptr, pS);

    tail_kernel<<<dim3(16, 16, N_IMG), 256>>>(pS, out_w, out_b, out);
}